// round 2
// baseline (speedup 1.0000x reference)
#include <cuda_runtime.h>
#include <math.h>

#define H   2048
#define V   50257
#define LL  80
#define H4  (H/4)      // 512 float4 per H-length vector
#define NRED 64        // partial-reduction blocks for log-softmax

// ---------------- scratch (device globals — no allocation allowed) ----------
__device__ float g_attn_logits[LL];
__device__ float g_attn_applied[H];
__device__ float g_lstm_in[H];
__device__ float g_h_new[H];
__device__ float g_logits[V];
__device__ float g_pmax[NRED];
__device__ float g_psum[NRED];
__device__ float g_red[2];   // [0] = global max, [1] = global sum exp

// ---------------- helpers ----------------
__device__ __forceinline__ float warp_reduce_add(float v) {
    v += __shfl_xor_sync(0xffffffffu, v, 16);
    v += __shfl_xor_sync(0xffffffffu, v, 8);
    v += __shfl_xor_sync(0xffffffffu, v, 4);
    v += __shfl_xor_sync(0xffffffffu, v, 2);
    v += __shfl_xor_sync(0xffffffffu, v, 1);
    return v;
}
__device__ __forceinline__ float warp_reduce_max(float v) {
    v = fmaxf(v, __shfl_xor_sync(0xffffffffu, v, 16));
    v = fmaxf(v, __shfl_xor_sync(0xffffffffu, v, 8));
    v = fmaxf(v, __shfl_xor_sync(0xffffffffu, v, 4));
    v = fmaxf(v, __shfl_xor_sync(0xffffffffu, v, 2));
    v = fmaxf(v, __shfl_xor_sync(0xffffffffu, v, 1));
    return v;
}

// dot of H floats (512 float4) done by one warp
__device__ __forceinline__ float warp_dot_H(const float4* __restrict__ a,
                                            const float4* __restrict__ b,
                                            int lane) {
    float acc = 0.f;
#pragma unroll 4
    for (int i = lane; i < H4; i += 32) {
        float4 x = __ldg(a + i);
        float4 y = __ldg(b + i);
        acc = fmaf(x.x, y.x, acc);
        acc = fmaf(x.y, y.y, acc);
        acc = fmaf(x.z, y.z, acc);
        acc = fmaf(x.w, y.w, acc);
    }
    return warp_reduce_add(acc);
}

// ---------------- A1: attention logits -------------------------------------
// grid = LL blocks, 128 threads. logit[l] = [h0, emb] . attn_W[l] + attn_b[l]
__global__ void k_attn_logits(const int* __restrict__ x,
                              const float* __restrict__ emb_W,
                              const float* __restrict__ h,
                              const float* __restrict__ attn_W,
                              const float* __restrict__ attn_b) {
    int l = blockIdx.x;
    int t = threadIdx.x;
    const float4* emb4 = (const float4*)(emb_W + (long)x[0] * H);
    const float4* h4   = (const float4*)h;
    const float4* wA   = (const float4*)(attn_W + (long)l * 2 * H);        // vs h0
    const float4* wB   = wA + H4;                                          // vs emb
    float acc = 0.f;
#pragma unroll 4
    for (int i = t; i < H4; i += 128) {
        float4 a = __ldg(wA + i), va = __ldg(h4 + i);
        float4 b = __ldg(wB + i), vb = __ldg(emb4 + i);
        acc = fmaf(a.x, va.x, acc); acc = fmaf(a.y, va.y, acc);
        acc = fmaf(a.z, va.z, acc); acc = fmaf(a.w, va.w, acc);
        acc = fmaf(b.x, vb.x, acc); acc = fmaf(b.y, vb.y, acc);
        acc = fmaf(b.z, vb.z, acc); acc = fmaf(b.w, vb.w, acc);
    }
    __shared__ float s[4];
    acc = warp_reduce_add(acc);
    if ((t & 31) == 0) s[t >> 5] = acc;
    __syncthreads();
    if (t == 0)
        g_attn_logits[l] = s[0] + s[1] + s[2] + s[3] + __ldg(attn_b + l);
}

// ---------------- A2: softmax (recomputed per block) + attn_applied ---------
// grid = H/256 blocks, 256 threads. Each block recomputes the 80-wide softmax
// (cheap, L2-resident) then computes its 256 columns of attn_w @ enc.
// Block 0 additionally writes the attn-weights output slice.
__global__ void k_attn_apply(const float* __restrict__ enc,
                             float* __restrict__ out_attn) {
    __shared__ float w[LL];
    __shared__ float red[8];
    int t = threadIdx.x;

    // softmax over the 80 logits, computed by the whole block
    float v = (t < LL) ? g_attn_logits[t] : -INFINITY;
    float m = warp_reduce_max(v);
    if ((t & 31) == 0) red[t >> 5] = m;
    __syncthreads();
    float blockmax = fmaxf(fmaxf(red[0], red[1]), fmaxf(red[2], red[3]));
    float e = (t < LL) ? expf(v - blockmax) : 0.f;
    float s = warp_reduce_add(e);
    __syncthreads();
    if ((t & 31) == 0) red[t >> 5] = s;
    __syncthreads();
    float blocksum = red[0] + red[1] + red[2] + red[3];
    if (t < LL) {
        float wt = e / blocksum;
        w[t] = wt;
        if (blockIdx.x == 0) out_attn[t] = wt;
    }
    __syncthreads();

    int k = blockIdx.x * blockDim.x + t;
    if (k < H) {
        float acc = 0.f;
#pragma unroll 8
        for (int l = 0; l < LL; ++l)
            acc = fmaf(w[l], __ldg(enc + (long)l * H + k), acc);
        g_attn_applied[k] = acc;
    }
}

// ---------------- B: lstm_in = relu(comb_W @ [emb; attn_applied] + b) -------
// 256 threads = 8 warps, one row per warp
__global__ void k_combine(const int* __restrict__ x,
                          const float* __restrict__ emb_W,
                          const float* __restrict__ comb_W,
                          const float* __restrict__ comb_b) {
    int warp = threadIdx.x >> 5, lane = threadIdx.x & 31;
    int row = blockIdx.x * 8 + warp;
    if (row >= H) return;
    const float4* emb4 = (const float4*)(emb_W + (long)x[0] * H);
    const float4* ap4  = (const float4*)g_attn_applied;
    const float4* wA   = (const float4*)(comb_W + (long)row * 2 * H);
    const float4* wB   = wA + H4;
    float d = warp_dot_H(wA, emb4, lane) + warp_dot_H(wB, ap4, lane);
    if (lane == 0)
        g_lstm_in[row] = fmaxf(d + __ldg(comb_b + row), 0.f);
}

// ---------------- C: fused LSTM cell ----------------------------------------
// grid = H blocks, 128 threads (4 warps = gates i,f,g,o for index j)
__global__ void k_lstm(const float* __restrict__ h,
                       const float* __restrict__ c,
                       const float* __restrict__ W_ih,
                       const float* __restrict__ W_hh,
                       const float* __restrict__ b_ih,
                       const float* __restrict__ b_hh) {
    int j = blockIdx.x;
    int warp = threadIdx.x >> 5, lane = threadIdx.x & 31;
    long r = (long)warp * H + j;
    const float4* wi = (const float4*)(W_ih + r * H);
    const float4* wh = (const float4*)(W_hh + r * H);
    const float4* li = (const float4*)g_lstm_in;
    const float4* h4 = (const float4*)h;
    float d = warp_dot_H(wi, li, lane) + warp_dot_H(wh, h4, lane);
    __shared__ float gate[4];
    if (lane == 0) gate[warp] = d + __ldg(b_ih + r) + __ldg(b_hh + r);
    __syncthreads();
    if (threadIdx.x == 0) {
        float gi = gate[0], gf = gate[1], gg = gate[2], go = gate[3];
        float si = 1.f / (1.f + expf(-gi));
        float sf = 1.f / (1.f + expf(-gf));
        float so = 1.f / (1.f + expf(-go));
        float cn = sf * __ldg(c + j) + si * tanhf(gg);
        g_h_new[j] = so * tanhf(cn);
    }
}

// ---------------- D: output projection (dominant GEMV) ----------------------
// 256 threads = 8 warps, one vocab row per warp
__global__ void k_logits(const float* __restrict__ out_W,
                         const float* __restrict__ out_b) {
    int warp = threadIdx.x >> 5, lane = threadIdx.x & 31;
    int row = blockIdx.x * 8 + warp;
    if (row >= V) return;
    const float4* w  = (const float4*)(out_W + (long)row * H);
    const float4* hv = (const float4*)g_h_new;
    float acc = 0.f;
#pragma unroll 8
    for (int i = lane; i < H4; i += 32) {
        float4 a = __ldg(w + i);
        float4 b = __ldg(hv + i);
        acc = fmaf(a.x, b.x, acc);
        acc = fmaf(a.y, b.y, acc);
        acc = fmaf(a.z, b.z, acc);
        acc = fmaf(a.w, b.w, acc);
    }
    acc = warp_reduce_add(acc);
    if (lane == 0) g_logits[row] = acc + __ldg(out_b + row);
}

// ---------------- E: log-softmax over V (2 launches) ------------------------
// E1: per-block local max + sum exp(x - local max)
__global__ void k_red_partial() {                 // NRED blocks x 256
    int t = threadIdx.x;
    float m = -INFINITY;
    for (int i = blockIdx.x * 256 + t; i < V; i += NRED * 256)
        m = fmaxf(m, g_logits[i]);
    float wm = warp_reduce_max(m);
    __shared__ float sm[8];
    if ((t & 31) == 0) sm[t >> 5] = wm;
    __syncthreads();
    float bm = sm[0];
#pragma unroll
    for (int i = 1; i < 8; ++i) bm = fmaxf(bm, sm[i]);

    float s = 0.f;
    for (int i = blockIdx.x * 256 + t; i < V; i += NRED * 256)
        s += expf(g_logits[i] - bm);
    float ws = warp_reduce_add(s);
    __syncthreads();
    if ((t & 31) == 0) sm[t >> 5] = ws;
    __syncthreads();
    if (t == 0) {
        float r = 0.f;
#pragma unroll
        for (int i = 0; i < 8; ++i) r += sm[i];
        g_pmax[blockIdx.x] = bm;
        g_psum[blockIdx.x] = r;
    }
}
// E2: merge partials via log-sum-exp: S = sum s_b * exp(m_b - M)
__global__ void k_red_final() {                   // 1 block x 64
    int t = threadIdx.x;
    float m = g_pmax[t];
    float wm = warp_reduce_max(m);
    __shared__ float sm[2];
    if ((t & 31) == 0) sm[t >> 5] = wm;
    __syncthreads();
    float M = fmaxf(sm[0], sm[1]);
    float s = g_psum[t] * expf(m - M);
    float ws = warp_reduce_add(s);
    __shared__ float ss[2];
    if ((t & 31) == 0) ss[t >> 5] = ws;
    __syncthreads();
    if (t == 0) {
        g_red[0] = M;
        g_red[1] = ss[0] + ss[1];
    }
}
__global__ void k_write_logp(float* __restrict__ out) {   // grid covers V
    int i = blockIdx.x * blockDim.x + threadIdx.x;
    if (i < V) {
        float shift = g_red[0] + logf(g_red[1]);
        out[i] = g_logits[i] - shift;
    }
}

// ---------------- launch -----------------------------------------------------
extern "C" void kernel_launch(void* const* d_in, const int* in_sizes, int n_in,
                              void* d_out, int out_size) {
    const int*   x      = (const int*)  d_in[0];
    const float* enc    = (const float*)d_in[1];
    const float* h      = (const float*)d_in[2];
    const float* c      = (const float*)d_in[3];
    const float* emb_W  = (const float*)d_in[4];
    const float* attn_W = (const float*)d_in[5];
    const float* attn_b = (const float*)d_in[6];
    const float* comb_W = (const float*)d_in[7];
    const float* comb_b = (const float*)d_in[8];
    const float* W_ih   = (const float*)d_in[9];
    const float* W_hh   = (const float*)d_in[10];
    const float* b_ih   = (const float*)d_in[11];
    const float* b_hh   = (const float*)d_in[12];
    const float* out_W  = (const float*)d_in[13];
    const float* out_b  = (const float*)d_in[14];
    float* out = (float*)d_out;

    k_attn_logits<<<LL, 128>>>(x, emb_W, h, attn_W, attn_b);
    k_attn_apply<<<(H + 255) / 256, 256>>>(enc, out + V);   // softmax fused
    k_combine<<<(H + 7) / 8, 256>>>(x, emb_W, comb_W, comb_b);
    k_lstm<<<H, 128>>>(h, c, W_ih, W_hh, b_ih, b_hh);
    k_logits<<<(V + 7) / 8, 256>>>(out_W, out_b);
    k_red_partial<<<NRED, 256>>>();
    k_red_final<<<1, 64>>>();
    k_write_logp<<<(V + 255) / 256, 256>>>(out);
}